// round 14
// baseline (speedup 1.0000x reference)
#include <cuda_runtime.h>
#include <cuda_bf16.h>
#include <cstdint>

// Cross-stitch: per-channel 2x2 mix.
//   out_a[n,c,h,w] = w[c,0,0]*x_a + w[c,0,1]*x_b
//   out_b[n,c,h,w] = w[c,1,0]*x_a + w[c,1,1]*x_b
// Shapes: x_a, x_b: [32, 256, 64, 64] fp32. weights: [256, 2, 2] fp32.
// Output: out_a followed by out_b.
//
// FINAL — ROOFLINE-COMPLETE (13 rounds of evidence):
// Pure 537MB 50/50 R/W stream at the traffic floor. Seven identical-source
// runs (R3/R6/R8/R10/R11/R12/R13): 73.8/75.1/75.6/77.9/73.7/79.7/75.1us —
// bimodal by container clock state (fast mode 73.7-75.6us @ L1~40%/
// issue~10%; slow mode 77.9-79.7us @ L1~64%/issue~16%, same SASS -> DVFS,
// environmental). Fast-mode achieved DRAM: 6.5TB/s (82.6% of 8TB/s spec);
// residual is controller-side R/W-turnaround + refresh, not programmable
// from the SM.
// Winning config: 256-bit global accesses (ld/st.global.v8.f32, sm_100+),
// evict-first both paths, 1 float8 chunk/thread, flat 16384x256 grid.
// Probed and rejected: .nc read path (neutral), 2-4 chunk batching /
// read-ahead pipelining (neutral to -2%), default cache policy (neutral),
// occupancy 48-80% (insensitive), 512-thread blocks (neutral),
// persistent grid-stride (-9%: loop-carried serialization; the flat grid's
// HW scheduler pipelines a pure stream better than software persistence).

static constexpr int C_ = 256;
static constexpr long long TOT  = 32LL * 256 * 64 * 64;   // 33,554,432 floats
static constexpr long long TOT8 = TOT / 8;                // 4,194,304 float8

__device__ __forceinline__ void ldg256_cs(const float* __restrict__ p, float r[8]) {
    asm volatile("ld.global.cs.v8.f32 {%0,%1,%2,%3,%4,%5,%6,%7}, [%8];"
                 : "=f"(r[0]), "=f"(r[1]), "=f"(r[2]), "=f"(r[3]),
                   "=f"(r[4]), "=f"(r[5]), "=f"(r[6]), "=f"(r[7])
                 : "l"(p));
}

__device__ __forceinline__ void stg256_cs(float* __restrict__ p, const float r[8]) {
    asm volatile("st.global.cs.v8.f32 [%0], {%1,%2,%3,%4,%5,%6,%7,%8};"
                 :: "l"(p),
                    "f"(r[0]), "f"(r[1]), "f"(r[2]), "f"(r[3]),
                    "f"(r[4]), "f"(r[5]), "f"(r[6]), "f"(r[7])
                 : "memory");
}

__global__ __launch_bounds__(256)
void cross_stitch_kernel(const float* __restrict__ xa,
                         const float* __restrict__ xb,
                         const float* __restrict__ w,   // [C,2,2]
                         float* __restrict__ oa,
                         float* __restrict__ ob)
{
    long long i8 = (long long)blockIdx.x * blockDim.x + threadIdx.x;  // float8 index
    long long off = i8 * 8;                                           // float offset

    // channel: float_index / 4096 mod 256 = (i8 >> 9) & 255
    int c = (int)((i8 >> 9) & (C_ - 1));
    const float* wc = w + c * 4;
    float w00 = __ldg(wc + 0);
    float w01 = __ldg(wc + 1);
    float w10 = __ldg(wc + 2);
    float w11 = __ldg(wc + 3);

    float a[8], b[8];
    ldg256_cs(xa + off, a);
    ldg256_cs(xb + off, b);

    float ra[8], rb[8];
#pragma unroll
    for (int k = 0; k < 8; k++) {
        ra[k] = fmaf(w00, a[k], w01 * b[k]);
        rb[k] = fmaf(w10, a[k], w11 * b[k]);
    }

    stg256_cs(oa + off, ra);
    stg256_cs(ob + off, rb);
}

extern "C" void kernel_launch(void* const* d_in, const int* in_sizes, int n_in,
                              void* d_out, int out_size)
{
    const float* xa = (const float*)d_in[0];
    const float* xb = (const float*)d_in[1];
    const float* w  = (const float*)d_in[2];

    float* oa = (float*)d_out;
    float* ob = oa + TOT;   // out_b follows out_a

    int threads = 256;
    long long blocks = TOT8 / threads;   // exact: 16384
    cross_stitch_kernel<<<(unsigned)blocks, threads>>>(xa, xb, w, oa, ob);
}

// round 15
// speedup vs baseline: 1.0004x; 1.0004x over previous
#include <cuda_runtime.h>
#include <cuda_bf16.h>
#include <cstdint>

// Cross-stitch: per-channel 2x2 mix.
//   out_a[n,c,h,w] = w[c,0,0]*x_a + w[c,0,1]*x_b
//   out_b[n,c,h,w] = w[c,1,0]*x_a + w[c,1,1]*x_b
// Shapes: x_a, x_b: [32, 256, 64, 64] fp32. weights: [256, 2, 2] fp32.
// Output: out_a followed by out_b.
//
// FINAL — ROOFLINE-COMPLETE (14 rounds of evidence):
// Pure 537MB 50/50 R/W stream at the traffic floor. Eight identical-source
// runs (R3/R6/R8/R10/R11/R12/R13/R14):
// 73.8/75.1/75.6/77.9/73.7/79.7/75.1/74.3us — bimodal by container clock
// state (fast mode 73.7-75.6us @ L1~40%/issue~10%; slow mode 77.9-79.7us @
// L1~64%/issue~16%, same SASS -> DVFS, environmental). Fast-mode achieved
// DRAM: 6.5TB/s (82.6% of 8TB/s spec); residual is controller-side
// R/W-turnaround + refresh, not programmable from the SM.
// Winning config: 256-bit global accesses (ld/st.global.v8.f32, sm_100+),
// evict-first both paths, 1 float8 chunk/thread, flat 16384x256 grid.
// Probed and rejected: .nc read path (neutral), 2-4 chunk batching /
// read-ahead pipelining (neutral to -2%), default cache policy (neutral),
// occupancy 48-80% (insensitive), 512-thread blocks (neutral),
// persistent grid-stride (-9%: loop-carried serialization; the flat grid's
// HW scheduler pipelines a pure stream better than software persistence).

static constexpr int C_ = 256;
static constexpr long long TOT  = 32LL * 256 * 64 * 64;   // 33,554,432 floats
static constexpr long long TOT8 = TOT / 8;                // 4,194,304 float8

__device__ __forceinline__ void ldg256_cs(const float* __restrict__ p, float r[8]) {
    asm volatile("ld.global.cs.v8.f32 {%0,%1,%2,%3,%4,%5,%6,%7}, [%8];"
                 : "=f"(r[0]), "=f"(r[1]), "=f"(r[2]), "=f"(r[3]),
                   "=f"(r[4]), "=f"(r[5]), "=f"(r[6]), "=f"(r[7])
                 : "l"(p));
}

__device__ __forceinline__ void stg256_cs(float* __restrict__ p, const float r[8]) {
    asm volatile("st.global.cs.v8.f32 [%0], {%1,%2,%3,%4,%5,%6,%7,%8};"
                 :: "l"(p),
                    "f"(r[0]), "f"(r[1]), "f"(r[2]), "f"(r[3]),
                    "f"(r[4]), "f"(r[5]), "f"(r[6]), "f"(r[7])
                 : "memory");
}

__global__ __launch_bounds__(256)
void cross_stitch_kernel(const float* __restrict__ xa,
                         const float* __restrict__ xb,
                         const float* __restrict__ w,   // [C,2,2]
                         float* __restrict__ oa,
                         float* __restrict__ ob)
{
    long long i8 = (long long)blockIdx.x * blockDim.x + threadIdx.x;  // float8 index
    long long off = i8 * 8;                                           // float offset

    // channel: float_index / 4096 mod 256 = (i8 >> 9) & 255
    int c = (int)((i8 >> 9) & (C_ - 1));
    const float* wc = w + c * 4;
    float w00 = __ldg(wc + 0);
    float w01 = __ldg(wc + 1);
    float w10 = __ldg(wc + 2);
    float w11 = __ldg(wc + 3);

    float a[8], b[8];
    ldg256_cs(xa + off, a);
    ldg256_cs(xb + off, b);

    float ra[8], rb[8];
#pragma unroll
    for (int k = 0; k < 8; k++) {
        ra[k] = fmaf(w00, a[k], w01 * b[k]);
        rb[k] = fmaf(w10, a[k], w11 * b[k]);
    }

    stg256_cs(oa + off, ra);
    stg256_cs(ob + off, rb);
}

extern "C" void kernel_launch(void* const* d_in, const int* in_sizes, int n_in,
                              void* d_out, int out_size)
{
    const float* xa = (const float*)d_in[0];
    const float* xb = (const float*)d_in[1];
    const float* w  = (const float*)d_in[2];

    float* oa = (float*)d_out;
    float* ob = oa + TOT;   // out_b follows out_a

    int threads = 256;
    long long blocks = TOT8 / threads;   // exact: 16384
    cross_stitch_kernel<<<(unsigned)blocks, threads>>>(xa, xb, w, oa, ob);
}